// round 2
// baseline (speedup 1.0000x reference)
#include <cuda_runtime.h>
#include <cstdint>
#include <cstddef>

#define BATCH 8
#define NPT   4096
#define KNB   16
#define CH    64
#define NCOL  (BATCH*NPT*KNB)        /* 524288 columns */
#define NGCTA (NCOL/256)             /* 2048 gemm CTAs */

/* ------------------------- device scratch (no allocs) ------------------- */
__device__ float4 d_psort[BATCH*NPT];          /* sorted (x,y,z,sq) desc by sq */
__device__ int    d_pidx [BATCH*NPT];          /* original index in sorted order */
__device__ float4 d_rel  [NCOL];               /* rel vectors (x,y,z,0) */
__device__ float  d_relstats[256*9];           /* per-knn-block partial moments */
__device__ float4 d_w0eff[CH];                 /* folded block-0: (wx,wy,wz,bias) */
__device__ float  d_z1[(size_t)CH*NCOL];       /* 128 MiB z1 scratch */
__device__ float  d_z1stats[NGCTA*CH*2];       /* per-CTA (sum,sumsq) per channel */
__device__ float2 d_a1c1[CH];                  /* folded BN-1 affine */

__device__ __forceinline__ float sq3(float x, float y, float z) {
    return __fadd_rn(__fadd_rn(__fmul_rn(x,x), __fmul_rn(y,y)), __fmul_rn(z,z));
}

/* ------------------------- 1. per-batch sort by |p|^2 desc --------------- */
__global__ __launch_bounds__(1024) void sort_kernel(const float* __restrict__ xyz) {
    __shared__ unsigned long long sk[NPT];
    int b = blockIdx.x;
    const float* xb = xyz + (size_t)b * 3 * NPT;
    for (int t = threadIdx.x; t < NPT; t += 1024) {
        float x = xb[t], y = xb[NPT + t], z = xb[2*NPT + t];
        float sq = sq3(x, y, z);                 /* sq >= 0: raw bits are order-preserving */
        sk[t] = ((unsigned long long)__float_as_uint(sq) << 32) | (unsigned int)t;
    }
    __syncthreads();
    for (int k = 2; k <= NPT; k <<= 1)
        for (int j = k >> 1; j > 0; j >>= 1) {
            for (int t = threadIdx.x; t < NPT; t += 1024) {
                int l = t ^ j;
                if (l > t) {
                    unsigned long long a = sk[t], c = sk[l];
                    bool up = ((t & k) == 0);
                    if ((a > c) == up) { sk[t] = c; sk[l] = a; }
                }
            }
            __syncthreads();
        }
    /* ascending in smem -> emit descending */
    for (int r = threadIdx.x; r < NPT; r += 1024) {
        unsigned long long kk = sk[NPT - 1 - r];
        int idx = (int)(unsigned int)kk;
        float sq = __uint_as_float((unsigned int)(kk >> 32));
        d_psort[(b << 12) + r] = make_float4(xb[idx], xb[NPT + idx], xb[2*NPT + idx], sq);
        d_pidx [(b << 12) + r] = idx;
    }
}

/* ------------------------- 2. kNN (farthest-16 after dropping rank 0) ---- */
__global__ __launch_bounds__(128) void knn_kernel(const float* __restrict__ xyz) {
    __shared__ float4 tP[512];
    __shared__ int    tI[512];
    __shared__ float  red[128];

    int b   = blockIdx.y;
    int tid = threadIdx.x;
    int i   = blockIdx.x * 128 + tid;
    const float* xb = xyz + (size_t)b * 3 * NPT;

    float px = xb[i], py = xb[NPT + i], pz = xb[2*NPT + i];
    float sqi  = sq3(px, py, pz);
    float si_r = sqrtf(sqi);

    unsigned long long heap[17];                 /* sorted desc; [0]=farthest */
    #pragma unroll
    for (int r = 0; r < 17; r++) heap[r] = 0ull;
    float thrF = __uint_as_float(0x7fffffffu);   /* NaN -> accept everything */
    float B2   = -1.0f;                          /* prune bound on sq_j */
    bool  dead = false;

    for (int t0 = 0; t0 < NPT; t0 += 512) {
        for (int s = tid; s < 512; s += 128) {
            tP[s] = d_psort[(b << 12) + t0 + s];
            tI[s] = d_pidx [(b << 12) + t0 + s];
        }
        __syncthreads();
        if (!__all_sync(0xffffffffu, dead)) {
            #pragma unroll 4
            for (int u = 0; u < 512; u++) {
                if (!dead) {
                    float4 q = tP[u];
                    if (q.w < B2) dead = true;       /* sq desc: all later pruned too */
                    else {
                        float dot = fmaf(pz, q.z, fmaf(py, q.y, __fmul_rn(px, q.x)));
                        float d   = __fsub_rn(__fadd_rn(sqi, q.w), __fmul_rn(2.0f, dot));
                        if (!(d < thrF)) {
                            int j2 = tI[u];
                            unsigned int bits = __float_as_uint(d);
                            unsigned int mono = bits ^ ((unsigned int)(((int)bits) >> 31) | 0x80000000u);
                            unsigned long long key =
                                ((unsigned long long)mono << 32) | (unsigned int)(~j2);
                            if (key > heap[16]) {
                                heap[16] = key;
                                #pragma unroll
                                for (int r = 16; r > 0; r--) {
                                    unsigned long long a_ = heap[r-1], c_ = heap[r];
                                    bool sw = c_ > a_;
                                    heap[r-1] = sw ? c_ : a_;
                                    heap[r]   = sw ? a_ : c_;
                                }
                                unsigned int h16 = (unsigned int)(heap[16] >> 32);
                                thrF = __uint_as_float((h16 & 0x80000000u) ? (h16 ^ 0x80000000u)
                                                                           : ~h16);
                                /* conservative prune bound: (si+sj)^2 < thr*(1-1e-4) */
                                float L   = __fmaf_rn(-1e-4f, thrF, thrF) - 1e-6f;
                                float sL  = sqrtf(L);
                                float bb2 = sL - si_r;
                                B2 = (bb2 > 0.0f) ? bb2 * bb2 : -1.0f;
                            }
                        }
                    }
                }
                if ((u & 63) == 63 && __all_sync(0xffffffffu, dead)) break;
            }
        }
        if (__syncthreads_and(dead)) break;      /* barrier + uniform early exit */
    }

    /* ranks 1..16 -> rel, moments */
    float sx=0,sy=0,sz=0,sxx=0,syy=0,szz=0,sxy=0,sxz=0,syz=0;
    size_t base = ((size_t)((b << 12) + i)) << 4;
    #pragma unroll
    for (int r = 1; r < 17; r++) {
        int j2 = ~((unsigned int)heap[r]);
        float rx = __fsub_rn(xb[j2],         px);
        float ry = __fsub_rn(xb[NPT  + j2],  py);
        float rz = __fsub_rn(xb[2*NPT + j2], pz);
        d_rel[base + (r - 1)] = make_float4(rx, ry, rz, 0.0f);
        sx += rx; sy += ry; sz += rz;
        sxx = fmaf(rx, rx, sxx); syy = fmaf(ry, ry, syy); szz = fmaf(rz, rz, szz);
        sxy = fmaf(rx, ry, sxy); sxz = fmaf(rx, rz, sxz); syz = fmaf(ry, rz, syz);
    }
    float st[9] = {sx, sy, sz, sxx, syy, szz, sxy, sxz, syz};
    int blk = b * 32 + blockIdx.x;
    for (int s = 0; s < 9; s++) {
        __syncthreads();
        red[tid] = st[s];
        __syncthreads();
        for (int off = 64; off; off >>= 1) {
            if (tid < off) red[tid] += red[tid + off];
            __syncthreads();
        }
        if (tid == 0) d_relstats[blk * 9 + s] = red[0];
    }
}

/* ------------------------- 3. fold block-0 conv+BN+relu ------------------ */
__global__ __launch_bounds__(64) void prep_kernel(const float* __restrict__ w1,
                                                  const float* __restrict__ b1,
                                                  const float* __restrict__ gamma,
                                                  const float* __restrict__ beta) {
    __shared__ double S[9];
    int t = threadIdx.x;
    if (t < 9) {
        double acc = 0.0;
        for (int v = 0; v < 256; v++) acc += (double)d_relstats[v * 9 + t];
        S[t] = acc;
    }
    __syncthreads();
    double inv = 1.0 / (double)NCOL;
    double mx = S[0]*inv, my = S[1]*inv, mz = S[2]*inv;
    double cxx = S[3]*inv - mx*mx, cyy = S[4]*inv - my*my, czz = S[5]*inv - mz*mz;
    double cxy = S[6]*inv - mx*my, cxz = S[7]*inv - mx*mz, cyz = S[8]*inv - my*mz;
    double wx = w1[t*3], wy = w1[t*3+1], wz = w1[t*3+2];
    double var = wx*(wx*cxx + 2.0*(wy*cxy + wz*cxz)) + wy*(wy*cyy + 2.0*wz*cyz) + wz*wz*czz;
    double mu  = wx*mx + wy*my + wz*mz + (double)b1[t];
    float aa = gamma[t] * rsqrtf((float)var + 1e-5f);
    float cc = beta[t] - (float)mu * aa;
    d_w0eff[t] = make_float4(aa*(float)wx, aa*(float)wy, aa*(float)wz, fmaf(aa, b1[t], cc));
}

/* ------------------------- 4. GEMM-1: z1 = w2*h0 + b2, + stats ----------- */
#define SW_STRIDE 68
#define SMEM_G ((CH*SW_STRIDE + CH*256 + 256) * 4)

__global__ __launch_bounds__(256) void gemm1_kernel(const float* __restrict__ w2,
                                                    const float* __restrict__ b2) {
    extern __shared__ float sm[];
    float*  sW = sm;                               /* [64][68] = w2^T */
    float*  sH = sm + CH*SW_STRIDE;                /* [64][256] h0 tile */
    float4* sE = (float4*)(sH + CH*256);           /* folded block-0 */
    int tid = threadIdx.x;
    #pragma unroll
    for (int s = 0; s < 16; s++) {
        int idx = tid + s*256;
        sW[(idx & 63)*SW_STRIDE + (idx >> 6)] = w2[idx];
    }
    if (tid < CH) sE[tid] = d_w0eff[tid];
    size_t c0 = (size_t)blockIdx.x * 256;
    float4 rel = d_rel[c0 + tid];
    __syncthreads();
    #pragma unroll 8
    for (int c = 0; c < CH; c++) {
        float4 w = sE[c];
        sH[c*256 + tid] =
            fmaxf(fmaf(w.z, rel.z, fmaf(w.y, rel.y, __fmul_rn(w.x, rel.x))) + w.w, 0.0f);
    }
    __syncthreads();

    int lane = tid & 31, warp = tid >> 5;
    int rb = warp * 8, cb = lane * 8;
    float acc[8][8];
    #pragma unroll
    for (int i = 0; i < 8; i++)
        #pragma unroll
        for (int j = 0; j < 8; j++) acc[i][j] = 0.0f;

    #pragma unroll 8
    for (int k = 0; k < CH; k++) {
        float4 a0 = *(const float4*)&sW[k*SW_STRIDE + rb];
        float4 a1 = *(const float4*)&sW[k*SW_STRIDE + rb + 4];
        float4 b0 = *(const float4*)&sH[k*256 + cb];
        float4 b1v= *(const float4*)&sH[k*256 + cb + 4];
        float A[8] = {a0.x,a0.y,a0.z,a0.w,a1.x,a1.y,a1.z,a1.w};
        float Bv[8]= {b0.x,b0.y,b0.z,b0.w,b1v.x,b1v.y,b1v.z,b1v.w};
        #pragma unroll
        for (int i = 0; i < 8; i++)
            #pragma unroll
            for (int j = 0; j < 8; j++)
                acc[i][j] = fmaf(A[i], Bv[j], acc[i][j]);
    }

    #pragma unroll
    for (int i = 0; i < 8; i++) {
        int row = rb + i;
        float bias = b2[row];
        float z[8];
        #pragma unroll
        for (int j = 0; j < 8; j++) z[j] = acc[i][j] + bias;
        float* dst = d_z1 + (size_t)row * NCOL + c0 + cb;
        *(float4*)dst     = make_float4(z[0], z[1], z[2], z[3]);
        *(float4*)(dst+4) = make_float4(z[4], z[5], z[6], z[7]);
        float s = 0.0f, s2 = 0.0f;
        #pragma unroll
        for (int j = 0; j < 8; j++) { s += z[j]; s2 = fmaf(z[j], z[j], s2); }
        #pragma unroll
        for (int off = 16; off; off >>= 1) {
            s  += __shfl_down_sync(0xffffffffu, s,  off);
            s2 += __shfl_down_sync(0xffffffffu, s2, off);
        }
        if (lane == 0) {
            d_z1stats[((size_t)blockIdx.x * CH + row) * 2]     = s;
            d_z1stats[((size_t)blockIdx.x * CH + row) * 2 + 1] = s2;
        }
    }
}

/* ------------------------- 5. fold BN-1 ---------------------------------- */
__global__ __launch_bounds__(128) void stats1_kernel(const float* __restrict__ gamma,
                                                     const float* __restrict__ beta) {
    __shared__ double S[128];
    int t = threadIdx.x;
    int ch = t & 63, which = t >> 6;
    double a0 = 0, a1 = 0, a2 = 0, a3 = 0;
    for (int v = 0; v < NGCTA; v += 4) {
        a0 += (double)d_z1stats[((size_t)(v    )*CH + ch)*2 + which];
        a1 += (double)d_z1stats[((size_t)(v + 1)*CH + ch)*2 + which];
        a2 += (double)d_z1stats[((size_t)(v + 2)*CH + ch)*2 + which];
        a3 += (double)d_z1stats[((size_t)(v + 3)*CH + ch)*2 + which];
    }
    S[t] = (a0 + a1) + (a2 + a3);
    __syncthreads();
    if (t < 64) {
        double mean = S[t] / (double)NCOL;
        double var  = S[64 + t] / (double)NCOL - mean * mean;
        float aa = gamma[t] * rsqrtf((float)var + 1e-5f);
        float cc = beta[t] - (float)mean * aa;
        d_a1c1[t] = make_float2(aa, cc);
    }
}

/* ------------------------- 6. GEMM-2 + max over k + output --------------- */
__global__ __launch_bounds__(256) void gemm2_kernel(const float* __restrict__ w2,
                                                    const float* __restrict__ b2,
                                                    float* __restrict__ out) {
    extern __shared__ float sm[];
    float*  sW  = sm;
    float*  sH  = sm + CH*SW_STRIDE;
    float2* sAC = (float2*)(sH + CH*256);
    int tid = threadIdx.x;
    #pragma unroll
    for (int s = 0; s < 16; s++) {
        int idx = tid + s*256;
        sW[(idx & 63)*SW_STRIDE + (idx >> 6)] = w2[idx];
    }
    if (tid < CH) sAC[tid] = d_a1c1[tid];
    __syncthreads();
    size_t c0 = (size_t)blockIdx.x * 256;
    #pragma unroll
    for (int s = 0; s < 16; s++) {
        int idx = tid + s*256;                    /* [64 rows][64 float4] */
        int r = idx >> 6, c4 = idx & 63;
        float4 v = *(const float4*)(d_z1 + (size_t)r * NCOL + c0 + ((size_t)c4 << 2));
        float2 ac = sAC[r];
        float4 h;
        h.x = fmaxf(fmaf(ac.x, v.x, ac.y), 0.0f);
        h.y = fmaxf(fmaf(ac.x, v.y, ac.y), 0.0f);
        h.z = fmaxf(fmaf(ac.x, v.z, ac.y), 0.0f);
        h.w = fmaxf(fmaf(ac.x, v.w, ac.y), 0.0f);
        *(float4*)&sH[r*256 + (c4 << 2)] = h;
    }
    __syncthreads();

    int lane = tid & 31, warp = tid >> 5;
    int rb = warp * 8, cb = lane * 8;
    float acc[8][8];
    #pragma unroll
    for (int i = 0; i < 8; i++)
        #pragma unroll
        for (int j = 0; j < 8; j++) acc[i][j] = 0.0f;

    #pragma unroll 8
    for (int k = 0; k < CH; k++) {
        float4 a0 = *(const float4*)&sW[k*SW_STRIDE + rb];
        float4 a1 = *(const float4*)&sW[k*SW_STRIDE + rb + 4];
        float4 b0 = *(const float4*)&sH[k*256 + cb];
        float4 b1v= *(const float4*)&sH[k*256 + cb + 4];
        float A[8] = {a0.x,a0.y,a0.z,a0.w,a1.x,a1.y,a1.z,a1.w};
        float Bv[8]= {b0.x,b0.y,b0.z,b0.w,b1v.x,b1v.y,b1v.z,b1v.w};
        #pragma unroll
        for (int i = 0; i < 8; i++)
            #pragma unroll
            for (int j = 0; j < 8; j++)
                acc[i][j] = fmaf(A[i], Bv[j], acc[i][j]);
    }

    /* lane pair (2l, 2l+1) covers the 16 k-slots of one point */
    int gi = (int)(c0 >> 4) + (lane >> 1);
    int bb_ = gi >> 12, ii = gi & 4095;
    #pragma unroll
    for (int i = 0; i < 8; i++) {
        int row = rb + i;
        float m = acc[i][0];
        #pragma unroll
        for (int j = 1; j < 8; j++) m = fmaxf(m, acc[i][j]);
        m += b2[row];
        float o2 = __shfl_xor_sync(0xffffffffu, m, 1);
        m = fmaxf(m, o2);
        if ((lane & 1) == 0)
            out[((size_t)(bb_ * CH + row) << 12) + ii] = m;
    }
}

/* ------------------------- launch ---------------------------------------- */
extern "C" void kernel_launch(void* const* d_in, const int* in_sizes, int n_in,
                              void* d_out, int out_size) {
    const float* xyz   = (const float*)d_in[0];
    const float* w1    = (const float*)d_in[1];
    const float* b1    = (const float*)d_in[2];
    const float* w2    = (const float*)d_in[3];
    const float* b2    = (const float*)d_in[4];
    const float* gamma = (const float*)d_in[5];
    const float* beta  = (const float*)d_in[6];
    float* out = (float*)d_out;

    cudaFuncSetAttribute(gemm1_kernel, cudaFuncAttributeMaxDynamicSharedMemorySize, SMEM_G);
    cudaFuncSetAttribute(gemm2_kernel, cudaFuncAttributeMaxDynamicSharedMemorySize, SMEM_G);

    sort_kernel<<<BATCH, 1024>>>(xyz);
    knn_kernel<<<dim3(32, BATCH), 128>>>(xyz);
    prep_kernel<<<1, 64>>>(w1, b1, gamma, beta);
    gemm1_kernel<<<NGCTA, 256, SMEM_G>>>(w2, b2);
    stats1_kernel<<<1, 128>>>(gamma, beta);
    gemm2_kernel<<<NGCTA, 256, SMEM_G>>>(w2, b2, out);
}

// round 3
// speedup vs baseline: 1.5457x; 1.5457x over previous
#include <cuda_runtime.h>
#include <cstdint>
#include <cstddef>

#define BATCH 8
#define NPT   4096
#define KNB   16
#define CH    64
#define NCOL  (BATCH*NPT*KNB)        /* 524288 columns */
#define NGCTA (NCOL/256)             /* 2048 gemm CTAs */

/* ------------------------- device scratch (no allocs) ------------------- */
__device__ float4 d_psort[BATCH*NPT];
__device__ int    d_pidx [BATCH*NPT];
__device__ float4 d_rel  [NCOL];
__device__ float  d_relstats[256*9];
__device__ float4 d_w0eff[CH];
__device__ float  d_z1[(size_t)CH*NCOL];       /* 128 MiB z1 scratch */
__device__ float  d_z1stats[NGCTA*CH*2];
__device__ double d_z1stats2[64*128];
__device__ float2 d_a1c1[CH];

__device__ __forceinline__ float sq3(float x, float y, float z) {
    return __fadd_rn(__fadd_rn(__fmul_rn(x,x), __fmul_rn(y,y)), __fmul_rn(z,z));
}

/* packed fp32x2 helpers (sm_100+) */
__device__ __forceinline__ unsigned long long bc2(float x) {
    unsigned long long r;
    asm("mov.b64 %0, {%1, %1};" : "=l"(r) : "f"(x));
    return r;
}
__device__ __forceinline__ void fma2(unsigned long long& d,
                                     unsigned long long a, unsigned long long b) {
    asm("fma.rn.f32x2 %0, %1, %2, %0;" : "+l"(d) : "l"(a), "l"(b));
}
__device__ __forceinline__ float2 unpk(unsigned long long v) {
    float2 r;
    asm("mov.b64 {%0, %1}, %2;" : "=f"(r.x), "=f"(r.y) : "l"(v));
    return r;
}

/* ------------------------- 1. per-batch sort by |p|^2 desc --------------- */
__global__ __launch_bounds__(1024) void sort_kernel(const float* __restrict__ xyz) {
    __shared__ unsigned long long sk[NPT];
    int b = blockIdx.x;
    const float* xb = xyz + (size_t)b * 3 * NPT;
    for (int t = threadIdx.x; t < NPT; t += 1024) {
        float x = xb[t], y = xb[NPT + t], z = xb[2*NPT + t];
        float sq = sq3(x, y, z);
        sk[t] = ((unsigned long long)__float_as_uint(sq) << 32) | (unsigned int)t;
    }
    __syncthreads();
    for (int k = 2; k <= NPT; k <<= 1)
        for (int j = k >> 1; j > 0; j >>= 1) {
            for (int t = threadIdx.x; t < NPT; t += 1024) {
                int l = t ^ j;
                if (l > t) {
                    unsigned long long a = sk[t], c = sk[l];
                    bool up = ((t & k) == 0);
                    if ((a > c) == up) { sk[t] = c; sk[l] = a; }
                }
            }
            __syncthreads();
        }
    for (int r = threadIdx.x; r < NPT; r += 1024) {
        unsigned long long kk = sk[NPT - 1 - r];
        int idx = (int)(unsigned int)kk;
        float sq = __uint_as_float((unsigned int)(kk >> 32));
        d_psort[(b << 12) + r] = make_float4(xb[idx], xb[NPT + idx], xb[2*NPT + idx], sq);
        d_pidx [(b << 12) + r] = idx;
    }
}

/* ------------------------- 2. kNN (farthest-16 after dropping rank 0) ---- */
__global__ __launch_bounds__(128) void knn_kernel(const float* __restrict__ xyz) {
    __shared__ float4 tP[512];
    __shared__ int    tI[512];
    __shared__ float  red[128];

    int b   = blockIdx.y;
    int tid = threadIdx.x;
    int i   = blockIdx.x * 128 + tid;
    const float* xb = xyz + (size_t)b * 3 * NPT;

    float px = xb[i], py = xb[NPT + i], pz = xb[2*NPT + i];
    float sqi  = sq3(px, py, pz);
    float si_r = sqrtf(sqi);

    unsigned long long heap[17];
    #pragma unroll
    for (int r = 0; r < 17; r++) heap[r] = 0ull;
    float thrF = __uint_as_float(0x7fffffffu);   /* NaN -> accept everything */
    float B2   = -1.0f;
    bool  dead = false;

    for (int t0 = 0; t0 < NPT; t0 += 512) {
        for (int s = tid; s < 512; s += 128) {
            tP[s] = d_psort[(b << 12) + t0 + s];
            tI[s] = d_pidx [(b << 12) + t0 + s];
        }
        __syncthreads();
        if (!__all_sync(0xffffffffu, dead)) {
            #pragma unroll 4
            for (int u = 0; u < 512; u++) {
                if (!dead) {
                    float4 q = tP[u];
                    if (q.w < B2) dead = true;
                    else {
                        float dot = fmaf(pz, q.z, fmaf(py, q.y, __fmul_rn(px, q.x)));
                        float d   = __fsub_rn(__fadd_rn(sqi, q.w), __fmul_rn(2.0f, dot));
                        if (!(d < thrF)) {
                            int j2 = tI[u];
                            unsigned int bits = __float_as_uint(d);
                            unsigned int mono = bits ^ ((unsigned int)(((int)bits) >> 31) | 0x80000000u);
                            unsigned long long key =
                                ((unsigned long long)mono << 32) | (unsigned int)(~j2);
                            if (key > heap[16]) {
                                heap[16] = key;
                                #pragma unroll
                                for (int r = 16; r > 0; r--) {
                                    unsigned long long a_ = heap[r-1], c_ = heap[r];
                                    bool sw = c_ > a_;
                                    heap[r-1] = sw ? c_ : a_;
                                    heap[r]   = sw ? a_ : c_;
                                }
                                unsigned int h16 = (unsigned int)(heap[16] >> 32);
                                thrF = __uint_as_float((h16 & 0x80000000u) ? (h16 ^ 0x80000000u)
                                                                           : ~h16);
                                float L   = __fmaf_rn(-1e-4f, thrF, thrF) - 1e-6f;
                                float sL  = sqrtf(L);
                                float bb2 = sL - si_r;
                                B2 = (bb2 > 0.0f) ? bb2 * bb2 : -1.0f;
                            }
                        }
                    }
                }
                if ((u & 63) == 63 && __all_sync(0xffffffffu, dead)) break;
            }
        }
        if (__syncthreads_and(dead)) break;
    }

    float sx=0,sy=0,sz=0,sxx=0,syy=0,szz=0,sxy=0,sxz=0,syz=0;
    size_t base = ((size_t)((b << 12) + i)) << 4;
    #pragma unroll
    for (int r = 1; r < 17; r++) {
        int j2 = ~((unsigned int)heap[r]);
        float rx = __fsub_rn(xb[j2],         px);
        float ry = __fsub_rn(xb[NPT  + j2],  py);
        float rz = __fsub_rn(xb[2*NPT + j2], pz);
        d_rel[base + (r - 1)] = make_float4(rx, ry, rz, 0.0f);
        sx += rx; sy += ry; sz += rz;
        sxx = fmaf(rx, rx, sxx); syy = fmaf(ry, ry, syy); szz = fmaf(rz, rz, szz);
        sxy = fmaf(rx, ry, sxy); sxz = fmaf(rx, rz, sxz); syz = fmaf(ry, rz, syz);
    }
    float st[9] = {sx, sy, sz, sxx, syy, szz, sxy, sxz, syz};
    int blk = b * 32 + blockIdx.x;
    for (int s = 0; s < 9; s++) {
        __syncthreads();
        red[tid] = st[s];
        __syncthreads();
        for (int off = 64; off; off >>= 1) {
            if (tid < off) red[tid] += red[tid + off];
            __syncthreads();
        }
        if (tid == 0) d_relstats[blk * 9 + s] = red[0];
    }
}

/* ------------------------- 3. fold block-0 conv+BN+relu ------------------ */
__global__ __launch_bounds__(64) void prep_kernel(const float* __restrict__ w1,
                                                  const float* __restrict__ b1,
                                                  const float* __restrict__ gamma,
                                                  const float* __restrict__ beta) {
    __shared__ double S[9];
    int t = threadIdx.x;
    if (t < 9) {
        double acc = 0.0;
        for (int v = 0; v < 256; v++) acc += (double)d_relstats[v * 9 + t];
        S[t] = acc;
    }
    __syncthreads();
    double inv = 1.0 / (double)NCOL;
    double mx = S[0]*inv, my = S[1]*inv, mz = S[2]*inv;
    double cxx = S[3]*inv - mx*mx, cyy = S[4]*inv - my*my, czz = S[5]*inv - mz*mz;
    double cxy = S[6]*inv - mx*my, cxz = S[7]*inv - mx*mz, cyz = S[8]*inv - my*mz;
    double wx = w1[t*3], wy = w1[t*3+1], wz = w1[t*3+2];
    double var = wx*(wx*cxx + 2.0*(wy*cxy + wz*cxz)) + wy*(wy*cyy + 2.0*wz*cyz) + wz*wz*czz;
    double mu  = wx*mx + wy*my + wz*mz + (double)b1[t];
    float aa = gamma[t] * rsqrtf((float)var + 1e-5f);
    float cc = beta[t] - (float)mu * aa;
    d_w0eff[t] = make_float4(aa*(float)wx, aa*(float)wy, aa*(float)wz, fmaf(aa, b1[t], cc));
}

/* ------------------------- 4. GEMM-1: z1 = w2*h0 + b2, + stats ----------- */
#define SW_STRIDE 68
#define SMEM_G ((CH*SW_STRIDE + CH*256 + 256) * 4)

__global__ __launch_bounds__(256) void gemm1_kernel(const float* __restrict__ w2,
                                                    const float* __restrict__ b2) {
    extern __shared__ float sm[];
    float*  sW = sm;                               /* [64][68] = w2^T */
    float*  sH = sm + CH*SW_STRIDE;                /* [64][256] h0 tile */
    float4* sE = (float4*)(sH + CH*256);
    int tid = threadIdx.x;
    #pragma unroll
    for (int s = 0; s < 16; s++) {
        int idx = tid + s*256;
        sW[(idx & 63)*SW_STRIDE + (idx >> 6)] = w2[idx];
    }
    if (tid < CH) sE[tid] = d_w0eff[tid];
    size_t c0 = (size_t)blockIdx.x * 256;
    float4 rel = d_rel[c0 + tid];
    __syncthreads();
    #pragma unroll 8
    for (int c = 0; c < CH; c++) {
        float4 w = sE[c];
        sH[c*256 + tid] =
            fmaxf(fmaf(w.z, rel.z, fmaf(w.y, rel.y, __fmul_rn(w.x, rel.x))) + w.w, 0.0f);
    }
    __syncthreads();

    int lane = tid & 31, warp = tid >> 5;
    int rb = warp * 8, cb = lane * 8;
    unsigned long long acc2[4][8];                 /* [row-pair][col] */
    #pragma unroll
    for (int ip = 0; ip < 4; ip++)
        #pragma unroll
        for (int j = 0; j < 8; j++) acc2[ip][j] = 0ull;

    #pragma unroll 8
    for (int k = 0; k < CH; k++) {
        ulonglong2 a0 = *(const ulonglong2*)&sW[k*SW_STRIDE + rb];     /* (A0,A1),(A2,A3) */
        ulonglong2 a1 = *(const ulonglong2*)&sW[k*SW_STRIDE + rb + 4];
        float4 b0 = *(const float4*)&sH[k*256 + cb];
        float4 b1v= *(const float4*)&sH[k*256 + cb + 4];
        unsigned long long Ap[4] = {a0.x, a0.y, a1.x, a1.y};
        unsigned long long Bb[8] = {bc2(b0.x), bc2(b0.y), bc2(b0.z), bc2(b0.w),
                                    bc2(b1v.x), bc2(b1v.y), bc2(b1v.z), bc2(b1v.w)};
        #pragma unroll
        for (int ip = 0; ip < 4; ip++)
            #pragma unroll
            for (int j = 0; j < 8; j++)
                fma2(acc2[ip][j], Ap[ip], Bb[j]);
    }

    #pragma unroll
    for (int ip = 0; ip < 4; ip++) {
        int r0 = rb + 2*ip, r1 = r0 + 1;
        float blo = b2[r0], bhi = b2[r1];
        float zlo[8], zhi[8];
        #pragma unroll
        for (int j = 0; j < 8; j++) {
            float2 p = unpk(acc2[ip][j]);
            zlo[j] = p.x + blo;
            zhi[j] = p.y + bhi;
        }
        float* d0 = d_z1 + (size_t)r0 * NCOL + c0 + cb;
        float* d1 = d_z1 + (size_t)r1 * NCOL + c0 + cb;
        *(float4*)d0     = make_float4(zlo[0], zlo[1], zlo[2], zlo[3]);
        *(float4*)(d0+4) = make_float4(zlo[4], zlo[5], zlo[6], zlo[7]);
        *(float4*)d1     = make_float4(zhi[0], zhi[1], zhi[2], zhi[3]);
        *(float4*)(d1+4) = make_float4(zhi[4], zhi[5], zhi[6], zhi[7]);
        float s0 = 0, s20 = 0, s1 = 0, s21 = 0;
        #pragma unroll
        for (int j = 0; j < 8; j++) {
            s0 += zlo[j]; s20 = fmaf(zlo[j], zlo[j], s20);
            s1 += zhi[j]; s21 = fmaf(zhi[j], zhi[j], s21);
        }
        #pragma unroll
        for (int off = 16; off; off >>= 1) {
            s0  += __shfl_down_sync(0xffffffffu, s0,  off);
            s20 += __shfl_down_sync(0xffffffffu, s20, off);
            s1  += __shfl_down_sync(0xffffffffu, s1,  off);
            s21 += __shfl_down_sync(0xffffffffu, s21, off);
        }
        if (lane == 0) {
            d_z1stats[((size_t)blockIdx.x * CH + r0) * 2]     = s0;
            d_z1stats[((size_t)blockIdx.x * CH + r0) * 2 + 1] = s20;
            d_z1stats[((size_t)blockIdx.x * CH + r1) * 2]     = s1;
            d_z1stats[((size_t)blockIdx.x * CH + r1) * 2 + 1] = s21;
        }
    }
}

/* ------------------------- 5. fold BN-1 (two-stage reduction) ------------ */
__global__ __launch_bounds__(128) void statsA_kernel() {
    int t = threadIdx.x;
    int ch = t & 63, which = t >> 6;
    int base = blockIdx.x * 32;
    double acc = 0.0;
    for (int v = 0; v < 32; v++)
        acc += (double)d_z1stats[((size_t)(base + v) * CH + ch) * 2 + which];
    d_z1stats2[blockIdx.x * 128 + t] = acc;
}

__global__ __launch_bounds__(128) void stats1_kernel(const float* __restrict__ gamma,
                                                     const float* __restrict__ beta) {
    __shared__ double S[128];
    int t = threadIdx.x;
    double acc = 0.0;
    #pragma unroll 8
    for (int c = 0; c < 64; c++) acc += d_z1stats2[c * 128 + t];
    S[t] = acc;
    __syncthreads();
    if (t < 64) {
        double mean = S[t] / (double)NCOL;
        double var  = S[64 + t] / (double)NCOL - mean * mean;
        float aa = gamma[t] * rsqrtf((float)var + 1e-5f);
        float cc = beta[t] - (float)mean * aa;
        d_a1c1[t] = make_float2(aa, cc);
    }
}

/* ------------------------- 6. GEMM-2 + max over k + output --------------- */
__global__ __launch_bounds__(256) void gemm2_kernel(const float* __restrict__ w2,
                                                    const float* __restrict__ b2,
                                                    float* __restrict__ out) {
    extern __shared__ float sm[];
    float*  sW  = sm;
    float*  sH  = sm + CH*SW_STRIDE;
    float2* sAC = (float2*)(sH + CH*256);
    int tid = threadIdx.x;
    #pragma unroll
    for (int s = 0; s < 16; s++) {
        int idx = tid + s*256;
        sW[(idx & 63)*SW_STRIDE + (idx >> 6)] = w2[idx];
    }
    if (tid < CH) sAC[tid] = d_a1c1[tid];
    __syncthreads();
    size_t c0 = (size_t)blockIdx.x * 256;
    #pragma unroll
    for (int s = 0; s < 16; s++) {
        int idx = tid + s*256;
        int r = idx >> 6, c4 = idx & 63;
        float4 v = *(const float4*)(d_z1 + (size_t)r * NCOL + c0 + ((size_t)c4 << 2));
        float2 ac = sAC[r];
        float4 h;
        h.x = fmaxf(fmaf(ac.x, v.x, ac.y), 0.0f);
        h.y = fmaxf(fmaf(ac.x, v.y, ac.y), 0.0f);
        h.z = fmaxf(fmaf(ac.x, v.z, ac.y), 0.0f);
        h.w = fmaxf(fmaf(ac.x, v.w, ac.y), 0.0f);
        *(float4*)&sH[r*256 + (c4 << 2)] = h;
    }
    __syncthreads();

    int lane = tid & 31, warp = tid >> 5;
    int rb = warp * 8, cb = lane * 8;
    unsigned long long acc2[4][8];
    #pragma unroll
    for (int ip = 0; ip < 4; ip++)
        #pragma unroll
        for (int j = 0; j < 8; j++) acc2[ip][j] = 0ull;

    #pragma unroll 8
    for (int k = 0; k < CH; k++) {
        ulonglong2 a0 = *(const ulonglong2*)&sW[k*SW_STRIDE + rb];
        ulonglong2 a1 = *(const ulonglong2*)&sW[k*SW_STRIDE + rb + 4];
        float4 b0 = *(const float4*)&sH[k*256 + cb];
        float4 b1v= *(const float4*)&sH[k*256 + cb + 4];
        unsigned long long Ap[4] = {a0.x, a0.y, a1.x, a1.y};
        unsigned long long Bb[8] = {bc2(b0.x), bc2(b0.y), bc2(b0.z), bc2(b0.w),
                                    bc2(b1v.x), bc2(b1v.y), bc2(b1v.z), bc2(b1v.w)};
        #pragma unroll
        for (int ip = 0; ip < 4; ip++)
            #pragma unroll
            for (int j = 0; j < 8; j++)
                fma2(acc2[ip][j], Ap[ip], Bb[j]);
    }

    /* lane pair (2l, 2l+1) covers the 16 k-slots of one point */
    int gi = (int)(c0 >> 4) + (lane >> 1);
    int bb_ = gi >> 12, ii = gi & 4095;
    #pragma unroll
    for (int ip = 0; ip < 4; ip++) {
        int r0 = rb + 2*ip, r1 = r0 + 1;
        float2 p0 = unpk(acc2[ip][0]);
        float mlo = p0.x, mhi = p0.y;
        #pragma unroll
        for (int j = 1; j < 8; j++) {
            float2 p = unpk(acc2[ip][j]);
            mlo = fmaxf(mlo, p.x);
            mhi = fmaxf(mhi, p.y);
        }
        mlo += b2[r0];
        mhi += b2[r1];
        float olo = __shfl_xor_sync(0xffffffffu, mlo, 1);
        float ohi = __shfl_xor_sync(0xffffffffu, mhi, 1);
        mlo = fmaxf(mlo, olo);
        mhi = fmaxf(mhi, ohi);
        if ((lane & 1) == 0) {
            out[((size_t)(bb_ * CH + r0) << 12) + ii] = mlo;
            out[((size_t)(bb_ * CH + r1) << 12) + ii] = mhi;
        }
    }
}

/* ------------------------- launch ---------------------------------------- */
extern "C" void kernel_launch(void* const* d_in, const int* in_sizes, int n_in,
                              void* d_out, int out_size) {
    const float* xyz   = (const float*)d_in[0];
    const float* w1    = (const float*)d_in[1];
    const float* b1    = (const float*)d_in[2];
    const float* w2    = (const float*)d_in[3];
    const float* b2    = (const float*)d_in[4];
    const float* gamma = (const float*)d_in[5];
    const float* beta  = (const float*)d_in[6];
    float* out = (float*)d_out;

    cudaFuncSetAttribute(gemm1_kernel, cudaFuncAttributeMaxDynamicSharedMemorySize, SMEM_G);
    cudaFuncSetAttribute(gemm2_kernel, cudaFuncAttributeMaxDynamicSharedMemorySize, SMEM_G);

    sort_kernel<<<BATCH, 1024>>>(xyz);
    knn_kernel<<<dim3(32, BATCH), 128>>>(xyz);
    prep_kernel<<<1, 64>>>(w1, b1, gamma, beta);
    gemm1_kernel<<<NGCTA, 256, SMEM_G>>>(w2, b2);
    statsA_kernel<<<64, 128>>>();
    stats1_kernel<<<1, 128>>>(gamma, beta);
    gemm2_kernel<<<NGCTA, 256, SMEM_G>>>(w2, b2, out);
}

// round 5
// speedup vs baseline: 1.7399x; 1.1256x over previous
#include <cuda_runtime.h>
#include <cuda_bf16.h>
#include <cstdint>
#include <cstddef>

#define BATCH 8
#define NPT   4096
#define CH    64
#define NCOL  (BATCH*NPT*16)         /* 524288 columns */
#define NTIL  (NCOL/128)             /* 4096 tensor tiles */

/* ------------------------- device scratch (no allocs) ------------------- */
__device__ float4 d_psort[BATCH*NPT];
__device__ int    d_pidx [BATCH*NPT];
__device__ float4 d_rel  [NCOL];
__device__ float  d_relstats[256*9];
__device__ float4 d_w0eff[CH];
__device__ float  d_z1stats[(size_t)NTIL*128];
__device__ double d_z1stats2[64*128];
__device__ float2 d_a1c1[CH];

__device__ __forceinline__ float sq3(float x, float y, float z) {
    return __fadd_rn(__fadd_rn(__fmul_rn(x,x), __fmul_rn(y,y)), __fmul_rn(z,z));
}

/* ------------------------- warp-mma helpers (sm_80+ portable) ----------- */
__device__ __forceinline__ uint32_t smem_u32(const void* p) {
    uint32_t a;
    asm("{ .reg .u64 t; cvta.to.shared.u64 t, %1; cvt.u32.u64 %0, t; }" : "=r"(a) : "l"(p));
    return a;
}
#define SWZ(o) ((o) ^ (((o) >> 3) & 0x70))

__device__ __forceinline__ void ldsm4(uint32_t addr, uint32_t r[4]) {
    asm volatile("ldmatrix.sync.aligned.m8n8.x4.shared.b16 {%0,%1,%2,%3}, [%4];"
        : "=r"(r[0]), "=r"(r[1]), "=r"(r[2]), "=r"(r[3]) : "r"(addr));
}
__device__ __forceinline__ void mma_bf16(float* c, const uint32_t* a,
                                         uint32_t b0, uint32_t b1) {
    asm volatile("mma.sync.aligned.m16n8k16.row.col.f32.bf16.bf16.f32 "
        "{%0,%1,%2,%3}, {%4,%5,%6,%7}, {%8,%9}, {%0,%1,%2,%3};"
        : "+f"(c[0]), "+f"(c[1]), "+f"(c[2]), "+f"(c[3])
        : "r"(a[0]), "r"(a[1]), "r"(a[2]), "r"(a[3]), "r"(b0), "r"(b1));
}
__device__ __forceinline__ uint32_t pk(float a, float b) {
    __nv_bfloat162 h = __floats2bfloat162_rn(a, b);
    return *(uint32_t*)&h;
}
/* split (a,b) into bf16 hi+lo packed pairs (a in low half) */
__device__ __forceinline__ void split2(float a, float b, uint32_t& hi, uint32_t& lo) {
    __nv_bfloat16 ah = __float2bfloat16_rn(a), bh = __float2bfloat16_rn(b);
    float ar = a - __bfloat162float(ah), br = b - __bfloat162float(bh);
    hi = (uint32_t)__bfloat16_as_ushort(ah) | ((uint32_t)__bfloat16_as_ushort(bh) << 16);
    lo = pk(ar, br);
}

/* smem layout (bytes): A rows = 128 cols x 128B, B rows = 64 ch x 128B */
#define SM_AHI   0
#define SM_ALO   16384
#define SM_BHI   32768
#define SM_BLO   40960
#define SM_W0    49152
#define SM_STATS 50176
#define SM_AC    50176
#define SM_BIAS  50688
#define SMEM_G   52224

/* ------------------------- 1. per-batch sort by |p|^2 desc --------------- */
__global__ __launch_bounds__(1024) void sort_kernel(const float* __restrict__ xyz) {
    __shared__ unsigned long long sk[NPT];
    int b = blockIdx.x;
    const float* xb = xyz + (size_t)b * 3 * NPT;
    for (int t = threadIdx.x; t < NPT; t += 1024) {
        float x = xb[t], y = xb[NPT + t], z = xb[2*NPT + t];
        float sq = sq3(x, y, z);
        sk[t] = ((unsigned long long)__float_as_uint(sq) << 32) | (unsigned int)t;
    }
    __syncthreads();
    for (int k = 2; k <= NPT; k <<= 1)
        for (int j = k >> 1; j > 0; j >>= 1) {
            for (int t = threadIdx.x; t < NPT; t += 1024) {
                int l = t ^ j;
                if (l > t) {
                    unsigned long long a = sk[t], c = sk[l];
                    bool up = ((t & k) == 0);
                    if ((a > c) == up) { sk[t] = c; sk[l] = a; }
                }
            }
            __syncthreads();
        }
    for (int r = threadIdx.x; r < NPT; r += 1024) {
        unsigned long long kk = sk[NPT - 1 - r];
        int idx = (int)(unsigned int)kk;
        d_psort[(b << 12) + r] = make_float4(xb[idx], xb[NPT + idx], xb[2*NPT + idx],
                                             __uint_as_float((unsigned int)(kk >> 32)));
        d_pidx [(b << 12) + r] = idx;
    }
}

/* ------------------------- 2. kNN (farthest-16 after dropping rank 0) ---- */
__global__ __launch_bounds__(128) void knn_kernel(const float* __restrict__ xyz) {
    __shared__ float4 tP[512];
    __shared__ int    tI[512];
    __shared__ float  red[128];

    int b   = blockIdx.y;
    int tid = threadIdx.x;
    int i   = blockIdx.x * 128 + tid;
    const float* xb = xyz + (size_t)b * 3 * NPT;

    float px = xb[i], py = xb[NPT + i], pz = xb[2*NPT + i];
    float sqi  = sq3(px, py, pz);
    float si_r = sqrtf(sqi);

    unsigned long long heap[17];
    #pragma unroll
    for (int r = 0; r < 17; r++) heap[r] = 0ull;
    float thrF = __uint_as_float(0x7fffffffu);
    float B2   = -1.0f;
    bool  dead = false;

    for (int t0 = 0; t0 < NPT; t0 += 512) {
        for (int s = tid; s < 512; s += 128) {
            tP[s] = d_psort[(b << 12) + t0 + s];
            tI[s] = d_pidx [(b << 12) + t0 + s];
        }
        __syncthreads();
        if (!__all_sync(0xffffffffu, dead)) {
            #pragma unroll 4
            for (int u = 0; u < 512; u++) {
                if (!dead) {
                    float4 q = tP[u];
                    if (q.w < B2) dead = true;
                    else {
                        float dot = fmaf(pz, q.z, fmaf(py, q.y, __fmul_rn(px, q.x)));
                        float d   = __fsub_rn(__fadd_rn(sqi, q.w), __fmul_rn(2.0f, dot));
                        if (!(d < thrF)) {
                            int j2 = tI[u];
                            unsigned int bits = __float_as_uint(d);
                            unsigned int mono = bits ^ ((unsigned int)(((int)bits) >> 31) | 0x80000000u);
                            unsigned long long key =
                                ((unsigned long long)mono << 32) | (unsigned int)(~j2);
                            if (key > heap[16]) {
                                heap[16] = key;
                                #pragma unroll
                                for (int r = 16; r > 0; r--) {
                                    unsigned long long a_ = heap[r-1], c_ = heap[r];
                                    bool sw = c_ > a_;
                                    heap[r-1] = sw ? c_ : a_;
                                    heap[r]   = sw ? a_ : c_;
                                }
                                unsigned int h16 = (unsigned int)(heap[16] >> 32);
                                thrF = __uint_as_float((h16 & 0x80000000u) ? (h16 ^ 0x80000000u)
                                                                           : ~h16);
                                float L   = __fmaf_rn(-1e-4f, thrF, thrF) - 1e-6f;
                                float sL  = sqrtf(L);
                                float bb2 = sL - si_r;
                                B2 = (bb2 > 0.0f) ? bb2 * bb2 : -1.0f;
                            }
                        }
                    }
                }
                if ((u & 63) == 63 && __all_sync(0xffffffffu, dead)) break;
            }
        }
        if (__syncthreads_and(dead)) break;
    }

    float sx=0,sy=0,sz=0,sxx=0,syy=0,szz=0,sxy=0,sxz=0,syz=0;
    size_t base = ((size_t)((b << 12) + i)) << 4;
    #pragma unroll
    for (int r = 1; r < 17; r++) {
        int j2 = ~((unsigned int)heap[r]);
        float rx = __fsub_rn(xb[j2],         px);
        float ry = __fsub_rn(xb[NPT  + j2],  py);
        float rz = __fsub_rn(xb[2*NPT + j2], pz);
        d_rel[base + (r - 1)] = make_float4(rx, ry, rz, 0.0f);
        sx += rx; sy += ry; sz += rz;
        sxx = fmaf(rx, rx, sxx); syy = fmaf(ry, ry, syy); szz = fmaf(rz, rz, szz);
        sxy = fmaf(rx, ry, sxy); sxz = fmaf(rx, rz, sxz); syz = fmaf(ry, rz, syz);
    }
    float st[9] = {sx, sy, sz, sxx, syy, szz, sxy, sxz, syz};
    int blk = b * 32 + blockIdx.x;
    for (int s = 0; s < 9; s++) {
        __syncthreads();
        red[tid] = st[s];
        __syncthreads();
        for (int off = 64; off; off >>= 1) {
            if (tid < off) red[tid] += red[tid + off];
            __syncthreads();
        }
        if (tid == 0) d_relstats[blk * 9 + s] = red[0];
    }
}

/* ------------------------- 3. fold block-0 conv+BN+relu ------------------ */
__global__ __launch_bounds__(64) void prep_kernel(const float* __restrict__ w1,
                                                  const float* __restrict__ b1,
                                                  const float* __restrict__ gamma,
                                                  const float* __restrict__ beta) {
    __shared__ double S[9];
    int t = threadIdx.x;
    if (t < 9) {
        double acc = 0.0;
        for (int v = 0; v < 256; v++) acc += (double)d_relstats[v * 9 + t];
        S[t] = acc;
    }
    __syncthreads();
    double inv = 1.0 / (double)NCOL;
    double mx = S[0]*inv, my = S[1]*inv, mz = S[2]*inv;
    double cxx = S[3]*inv - mx*mx, cyy = S[4]*inv - my*my, czz = S[5]*inv - mz*mz;
    double cxy = S[6]*inv - mx*my, cxz = S[7]*inv - mx*mz, cyz = S[8]*inv - my*mz;
    double wx = w1[t*3], wy = w1[t*3+1], wz = w1[t*3+2];
    double var = wx*(wx*cxx + 2.0*(wy*cxy + wz*cxz)) + wy*(wy*cyy + 2.0*wz*cyz) + wz*wz*czz;
    double mu  = wx*mx + wy*my + wz*mz + (double)b1[t];
    float aa = gamma[t] * rsqrtf((float)var + 1e-5f);
    float cc = beta[t] - (float)mu * aa;
    d_w0eff[t] = make_float4(aa*(float)wx, aa*(float)wy, aa*(float)wz, fmaf(aa, b1[t], cc));
}

/* -------- shared device code: build A (h0 split) and B (w2 split) -------- */
__device__ __forceinline__ void build_B(char* smraw, const float* __restrict__ w2, int tid) {
    int n = tid >> 1, k0 = (tid & 1) * 32;
    const float* wrow = w2 + n * 64 + k0;
    #pragma unroll
    for (int k = 0; k < 32; k += 4) {
        float4 v = *(const float4*)(wrow + k);
        uint32_t h0, h1, l0, l1;
        split2(v.x, v.y, h0, l0); split2(v.z, v.w, h1, l1);
        uint32_t off = SWZ((uint32_t)(n * 128 + (k0 + k) * 2));
        *(uint2*)(smraw + SM_BHI + off) = make_uint2(h0, h1);
        *(uint2*)(smraw + SM_BLO + off) = make_uint2(l0, l1);
    }
}
__device__ __forceinline__ void build_A(char* smraw, const float4* w0, int tid, int T) {
    float4 rel = d_rel[(size_t)T * 128 + tid];
    #pragma unroll
    for (int c = 0; c < 64; c += 4) {
        float h[4];
        #pragma unroll
        for (int u = 0; u < 4; u++) {
            float4 w = w0[c + u];
            h[u] = fmaxf(fmaf(w.z, rel.z, fmaf(w.y, rel.y, __fmul_rn(w.x, rel.x))) + w.w, 0.0f);
        }
        uint32_t h0, h1, l0, l1;
        split2(h[0], h[1], h0, l0); split2(h[2], h[3], h1, l1);
        uint32_t off = SWZ((uint32_t)(tid * 128 + c * 2));
        *(uint2*)(smraw + SM_AHI + off) = make_uint2(h0, h1);
        *(uint2*)(smraw + SM_ALO + off) = make_uint2(l0, l1);
    }
}
/* 3-term split MMA over K=64 into acc[2][8][4] */
__device__ __forceinline__ void mma_layer(uint32_t smb, int wid, int lane,
                                          float acc[2][8][4]) {
    uint32_t rowA = wid * 32 + (lane & 15);
    uint32_t kbA  = (lane >> 4) * 8;
    uint32_t nB   = ((lane >> 4) * 8) + (lane & 7);
    uint32_t kbB  = ((lane >> 3) & 1) * 8;
    #pragma unroll
    for (int kt = 0; kt < 4; kt++) {
        uint32_t ah[2][4], al[2][4], bh[4][4], bl[4][4];
        #pragma unroll
        for (int mt = 0; mt < 2; mt++) {
            uint32_t off = SWZ((rowA + mt*16)*128 + (kbA + kt*16)*2);
            ldsm4(smb + SM_AHI + off, ah[mt]);
            ldsm4(smb + SM_ALO + off, al[mt]);
        }
        #pragma unroll
        for (int u = 0; u < 4; u++) {
            uint32_t off = SWZ((nB + u*16)*128 + (kbB + kt*16)*2);
            ldsm4(smb + SM_BHI + off, bh[u]);
            ldsm4(smb + SM_BLO + off, bl[u]);
        }
        #pragma unroll
        for (int mt = 0; mt < 2; mt++)
            #pragma unroll
            for (int j = 0; j < 8; j++) {
                int u = j >> 1, h2 = (j & 1) * 2;
                mma_bf16(acc[mt][j], ah[mt], bh[u][h2], bh[u][h2+1]);
                mma_bf16(acc[mt][j], ah[mt], bl[u][h2], bl[u][h2+1]);
                mma_bf16(acc[mt][j], al[mt], bh[u][h2], bh[u][h2+1]);
            }
    }
}

/* ------------------------- 4. GEMM-1: stats-only pass -------------------- */
__global__ __launch_bounds__(128, 2) void gemm1_kernel(const float* __restrict__ w2) {
    extern __shared__ char smraw[];
    uint32_t smb = smem_u32(smraw);
    float4* w0     = (float4*)(smraw + SM_W0);
    float*  wstats = (float*)(smraw + SM_STATS);
    int tid = threadIdx.x, wid = tid >> 5, lane = tid & 31;
    int T = blockIdx.x;

    if (tid < 64) w0[tid] = d_w0eff[tid];
    build_B(smraw, w2, tid);
    __syncthreads();
    build_A(smraw, w0, tid, T);
    __syncthreads();

    float acc[2][8][4];
    #pragma unroll
    for (int mt = 0; mt < 2; mt++)
        #pragma unroll
        for (int j = 0; j < 8; j++)
            #pragma unroll
            for (int v = 0; v < 4; v++) acc[mt][j][v] = 0.0f;
    mma_layer(smb, wid, lane, acc);

    int q = lane & 3;
    #pragma unroll
    for (int j = 0; j < 8; j++) {
        float s0 = (acc[0][j][0] + acc[0][j][2]) + (acc[1][j][0] + acc[1][j][2]);
        float s1 = (acc[0][j][1] + acc[0][j][3]) + (acc[1][j][1] + acc[1][j][3]);
        float q0 = fmaf(acc[0][j][0], acc[0][j][0], acc[0][j][2]*acc[0][j][2])
                 + fmaf(acc[1][j][0], acc[1][j][0], acc[1][j][2]*acc[1][j][2]);
        float q1 = fmaf(acc[0][j][1], acc[0][j][1], acc[0][j][3]*acc[0][j][3])
                 + fmaf(acc[1][j][1], acc[1][j][1], acc[1][j][3]*acc[1][j][3]);
        #pragma unroll
        for (int off = 4; off <= 16; off <<= 1) {
            s0 += __shfl_xor_sync(0xffffffffu, s0, off);
            s1 += __shfl_xor_sync(0xffffffffu, s1, off);
            q0 += __shfl_xor_sync(0xffffffffu, q0, off);
            q1 += __shfl_xor_sync(0xffffffffu, q1, off);
        }
        if (lane < 4) {
            int c0 = 8*j + 2*q;
            wstats[wid*128 + c0]          = s0;
            wstats[wid*128 + c0 + 1]      = s1;
            wstats[wid*128 + 64 + c0]     = q0;
            wstats[wid*128 + 64 + c0 + 1] = q1;
        }
    }
    __syncthreads();
    float a = wstats[tid] + wstats[128 + tid] + wstats[256 + tid] + wstats[384 + tid];
    d_z1stats[(size_t)T * 128 + tid] = a;
}

/* ------------------------- 5. fold BN-1 (two-stage reduce) --------------- */
__global__ __launch_bounds__(128) void statsA_kernel() {
    int t = threadIdx.x;
    int base = blockIdx.x * 64;
    double a = 0.0;
    for (int v = 0; v < 64; v++) a += (double)d_z1stats[(size_t)(base + v) * 128 + t];
    d_z1stats2[blockIdx.x * 128 + t] = a;
}

__global__ __launch_bounds__(128) void stats1_kernel(const float* __restrict__ gamma,
                                                     const float* __restrict__ beta) {
    __shared__ double S[128];
    int t = threadIdx.x;
    double acc = 0.0;
    #pragma unroll 8
    for (int c = 0; c < 64; c++) acc += d_z1stats2[c * 128 + t];
    S[t] = acc;
    __syncthreads();
    if (t < 64) {
        double mean = S[t] / (double)NCOL;             /* raw mean (no bias) */
        double var  = S[64 + t] / (double)NCOL - mean * mean;
        float aa = gamma[t] * rsqrtf((float)var + 1e-5f);
        float cc = beta[t] - (float)mean * aa;         /* bias folds out */
        d_a1c1[t] = make_float2(aa, cc);
    }
}

/* ------------------------- 6. GEMM-2: recompute + BN + MMA + max --------- */
__global__ __launch_bounds__(128, 2) void gemm2_kernel(const float* __restrict__ w2,
                                                       const float* __restrict__ b2,
                                                       float* __restrict__ out) {
    extern __shared__ char smraw[];
    uint32_t smb = smem_u32(smraw);
    float4* w0    = (float4*)(smraw + SM_W0);
    float2* ac    = (float2*)(smraw + SM_AC);
    float*  sbias = (float*)(smraw + SM_BIAS);
    int tid = threadIdx.x, wid = tid >> 5, lane = tid & 31;
    int T = blockIdx.x;

    if (tid < 64) { w0[tid] = d_w0eff[tid]; ac[tid] = d_a1c1[tid]; sbias[tid] = b2[tid]; }
    build_B(smraw, w2, tid);
    __syncthreads();
    build_A(smraw, w0, tid, T);
    __syncthreads();

    /* first MMA: raw z1 tile in registers */
    float acc1[2][8][4];
    #pragma unroll
    for (int mt = 0; mt < 2; mt++)
        #pragma unroll
        for (int j = 0; j < 8; j++)
            #pragma unroll
            for (int v = 0; v < 4; v++) acc1[mt][j][v] = 0.0f;
    mma_layer(smb, wid, lane, acc1);

    /* BN-1 affine + relu + bf16-split: D-fragments -> A-fragments (in-lane) */
    int q = lane & 3;
    uint32_t ahf[2][4][4], alf[2][4][4];
    #pragma unroll
    for (int mt = 0; mt < 2; mt++)
        #pragma unroll
        for (int kt = 0; kt < 4; kt++)
            #pragma unroll
            for (int half = 0; half < 2; half++) {
                int j = 2*kt + half;
                float2 c0 = ac[8*j + 2*q], c1 = ac[8*j + 2*q + 1];
                float v0 = fmaxf(fmaf(c0.x, acc1[mt][j][0], c0.y), 0.0f);
                float v1 = fmaxf(fmaf(c1.x, acc1[mt][j][1], c1.y), 0.0f);
                float v2 = fmaxf(fmaf(c0.x, acc1[mt][j][2], c0.y), 0.0f);
                float v3 = fmaxf(fmaf(c1.x, acc1[mt][j][3], c1.y), 0.0f);
                split2(v0, v1, ahf[mt][kt][half*2],     alf[mt][kt][half*2]);
                split2(v2, v3, ahf[mt][kt][half*2 + 1], alf[mt][kt][half*2 + 1]);
            }

    /* second MMA */
    float acc2[2][8][4];
    #pragma unroll
    for (int mt = 0; mt < 2; mt++)
        #pragma unroll
        for (int j = 0; j < 8; j++)
            #pragma unroll
            for (int v = 0; v < 4; v++) acc2[mt][j][v] = 0.0f;
    {
        uint32_t nB  = ((lane >> 4) * 8) + (lane & 7);
        uint32_t kbB = ((lane >> 3) & 1) * 8;
        #pragma unroll
        for (int kt = 0; kt < 4; kt++) {
            uint32_t bh[4][4], bl[4][4];
            #pragma unroll
            for (int u = 0; u < 4; u++) {
                uint32_t off = SWZ((nB + u*16)*128 + (kbB + kt*16)*2);
                ldsm4(smb + SM_BHI + off, bh[u]);
                ldsm4(smb + SM_BLO + off, bl[u]);
            }
            #pragma unroll
            for (int mt = 0; mt < 2; mt++)
                #pragma unroll
                for (int j = 0; j < 8; j++) {
                    int u = j >> 1, h2 = (j & 1) * 2;
                    mma_bf16(acc2[mt][j], ahf[mt][kt], bh[u][h2], bh[u][h2+1]);
                    mma_bf16(acc2[mt][j], ahf[mt][kt], bl[u][h2], bl[u][h2+1]);
                    mma_bf16(acc2[mt][j], alf[mt][kt], bh[u][h2], bh[u][h2+1]);
                }
        }
    }

    /* max over each m16 tile (= one point's 16 neighbors) + bias + store */
    #pragma unroll
    for (int mt = 0; mt < 2; mt++) {
        int g  = T * 8 + wid * 2 + mt;
        int bb = g >> 12, ii = g & 4095;
        #pragma unroll
        for (int j = 0; j < 8; j++) {
            float x = fmaxf(acc2[mt][j][0], acc2[mt][j][2]);
            float y = fmaxf(acc2[mt][j][1], acc2[mt][j][3]);
            #pragma unroll
            for (int off = 4; off <= 16; off <<= 1) {
                x = fmaxf(x, __shfl_xor_sync(0xffffffffu, x, off));
                y = fmaxf(y, __shfl_xor_sync(0xffffffffu, y, off));
            }
            if (lane < 4) {
                int c0 = 8*j + 2*lane;
                out[((size_t)(bb * CH + c0)     << 12) + ii] = x + sbias[c0];
                out[((size_t)(bb * CH + c0 + 1) << 12) + ii] = y + sbias[c0 + 1];
            }
        }
    }
}

/* ------------------------- launch ---------------------------------------- */
extern "C" void kernel_launch(void* const* d_in, const int* in_sizes, int n_in,
                              void* d_out, int out_size) {
    const float* xyz   = (const float*)d_in[0];
    const float* w1    = (const float*)d_in[1];
    const float* b1    = (const float*)d_in[2];
    const float* w2    = (const float*)d_in[3];
    const float* b2    = (const float*)d_in[4];
    const float* gamma = (const float*)d_in[5];
    const float* beta  = (const float*)d_in[6];
    float* out = (float*)d_out;

    cudaFuncSetAttribute(gemm1_kernel, cudaFuncAttributeMaxDynamicSharedMemorySize, SMEM_G);
    cudaFuncSetAttribute(gemm2_kernel, cudaFuncAttributeMaxDynamicSharedMemorySize, SMEM_G);

    sort_kernel<<<BATCH, 1024>>>(xyz);
    knn_kernel<<<dim3(32, BATCH), 128>>>(xyz);
    prep_kernel<<<1, 64>>>(w1, b1, gamma, beta);
    gemm1_kernel<<<NTIL, 128, SMEM_G>>>(w2);
    statsA_kernel<<<64, 128>>>();
    stats1_kernel<<<1, 128>>>(gamma, beta);
    gemm2_kernel<<<NTIL, 128, SMEM_G>>>(w2, b2, out);
}

// round 8
// speedup vs baseline: 1.7829x; 1.0247x over previous
#include <cuda_runtime.h>
#include <cuda_bf16.h>
#include <cstdint>
#include <cstddef>

#define BATCH 8
#define NPT   4096
#define CH    64
#define NCOL  (BATCH*NPT*16)         /* 524288 columns */
#define NTIL  (NCOL/128)             /* 4096 tensor tiles */
#define TPC   8                      /* tiles per CTA */
#define NGRID (NTIL/TPC)             /* 512 gemm CTAs */

/* ------------------------- device scratch (no allocs) ------------------- */
__device__ float4 d_psort[BATCH*NPT];
__device__ int    d_pidx [BATCH*NPT];
__device__ float4 d_rel  [NCOL];
__device__ float  d_relstats[256*9];
__device__ float4 d_w0eff[CH];
__device__ float  d_z1stats[(size_t)NGRID*128];
__device__ double d_z1stats2[64*128];
__device__ float2 d_a1c1[CH];

__device__ __forceinline__ float sq3(float x, float y, float z) {
    return __fadd_rn(__fadd_rn(__fmul_rn(x,x), __fmul_rn(y,y)), __fmul_rn(z,z));
}

/* ------------------------- warp-mma helpers (sm_80+ portable) ----------- */
__device__ __forceinline__ uint32_t smem_u32(const void* p) {
    uint32_t a;
    asm("{ .reg .u64 t; cvta.to.shared.u64 t, %1; cvt.u32.u64 %0, t; }" : "=r"(a) : "l"(p));
    return a;
}
#define SWZ(o) ((o) ^ (((o) >> 3) & 0x70))

__device__ __forceinline__ void ldsm4(uint32_t addr, uint32_t r[4]) {
    asm volatile("ldmatrix.sync.aligned.m8n8.x4.shared.b16 {%0,%1,%2,%3}, [%4];"
        : "=r"(r[0]), "=r"(r[1]), "=r"(r[2]), "=r"(r[3]) : "r"(addr));
}
__device__ __forceinline__ void mma_bf16(float* c, const uint32_t* a,
                                         uint32_t b0, uint32_t b1) {
    asm volatile("mma.sync.aligned.m16n8k16.row.col.f32.bf16.bf16.f32 "
        "{%0,%1,%2,%3}, {%4,%5,%6,%7}, {%8,%9}, {%0,%1,%2,%3};"
        : "+f"(c[0]), "+f"(c[1]), "+f"(c[2]), "+f"(c[3])
        : "r"(a[0]), "r"(a[1]), "r"(a[2]), "r"(a[3]), "r"(b0), "r"(b1));
}
__device__ __forceinline__ uint32_t pk(float a, float b) {
    __nv_bfloat162 h = __floats2bfloat162_rn(a, b);
    return *(uint32_t*)&h;
}
__device__ __forceinline__ void split2(float a, float b, uint32_t& hi, uint32_t& lo) {
    __nv_bfloat16 ah = __float2bfloat16_rn(a), bh = __float2bfloat16_rn(b);
    float ar = a - __bfloat162float(ah), br = b - __bfloat162float(bh);
    hi = (uint32_t)__bfloat16_as_ushort(ah) | ((uint32_t)__bfloat16_as_ushort(bh) << 16);
    lo = pk(ar, br);
}

/* smem layout (bytes) */
#define SM_AHI   0
#define SM_ALO   16384
#define SM_BHI   32768
#define SM_BLO   40960
#define SM_W0    49152
#define SM_STATS 50176
#define SM_AC    50176
#define SM_BIAS  50688
#define SMEM_G   52224

/* ------------------------- 1. per-batch sort by |p|^2 desc --------------- */
__global__ __launch_bounds__(1024) void sort_kernel(const float* __restrict__ xyz) {
    __shared__ unsigned long long sk[NPT];
    int b = blockIdx.x;
    const float* xb = xyz + (size_t)b * 3 * NPT;
    for (int t = threadIdx.x; t < NPT; t += 1024) {
        float x = xb[t], y = xb[NPT + t], z = xb[2*NPT + t];
        float sq = sq3(x, y, z);
        sk[t] = ((unsigned long long)__float_as_uint(sq) << 32) | (unsigned int)t;
    }
    __syncthreads();
    for (int k = 2; k <= NPT; k <<= 1)
        for (int j = k >> 1; j > 0; j >>= 1) {
            for (int t = threadIdx.x; t < NPT; t += 1024) {
                int l = t ^ j;
                if (l > t) {
                    unsigned long long a = sk[t], c = sk[l];
                    bool up = ((t & k) == 0);
                    if ((a > c) == up) { sk[t] = c; sk[l] = a; }
                }
            }
            __syncthreads();
        }
    for (int r = threadIdx.x; r < NPT; r += 1024) {
        unsigned long long kk = sk[NPT - 1 - r];
        int idx = (int)(unsigned int)kk;
        d_psort[(b << 12) + r] = make_float4(xb[idx], xb[NPT + idx], xb[2*NPT + idx],
                                             __uint_as_float((unsigned int)(kk >> 32)));
        d_pidx [(b << 12) + r] = idx;
    }
}

/* ------------------------- 2. kNN (farthest-16 after dropping rank 0) ---- */
__global__ __launch_bounds__(128) void knn_kernel(const float* __restrict__ xyz) {
    __shared__ float4 tP[512];
    __shared__ int    tI[512];
    __shared__ float  red[128];

    int b   = blockIdx.y;
    int tid = threadIdx.x;
    int i   = blockIdx.x * 128 + tid;
    const float* xb = xyz + (size_t)b * 3 * NPT;

    float px = xb[i], py = xb[NPT + i], pz = xb[2*NPT + i];
    float sqi  = sq3(px, py, pz);
    float si_r = sqrtf(sqi);

    unsigned long long heap[17];
    #pragma unroll
    for (int r = 0; r < 17; r++) heap[r] = 0ull;
    float thrF = __uint_as_float(0x7fffffffu);
    float B2   = -1.0f;
    bool  dead = false;

    for (int t0 = 0; t0 < NPT; t0 += 512) {
        for (int s = tid; s < 512; s += 128) {
            tP[s] = d_psort[(b << 12) + t0 + s];
            tI[s] = d_pidx [(b << 12) + t0 + s];
        }
        __syncthreads();
        if (!__all_sync(0xffffffffu, dead)) {
            #pragma unroll 4
            for (int u = 0; u < 512; u++) {
                if (!dead) {
                    float4 q = tP[u];
                    if (q.w < B2) dead = true;
                    else {
                        float dot = fmaf(pz, q.z, fmaf(py, q.y, __fmul_rn(px, q.x)));
                        float d   = __fsub_rn(__fadd_rn(sqi, q.w), __fmul_rn(2.0f, dot));
                        if (!(d < thrF)) {
                            int j2 = tI[u];
                            unsigned int bits = __float_as_uint(d);
                            unsigned int mono = bits ^ ((unsigned int)(((int)bits) >> 31) | 0x80000000u);
                            unsigned long long key =
                                ((unsigned long long)mono << 32) | (unsigned int)(~j2);
                            if (key > heap[16]) {
                                heap[16] = key;
                                #pragma unroll
                                for (int r = 16; r > 0; r--) {
                                    unsigned long long a_ = heap[r-1], c_ = heap[r];
                                    bool sw = c_ > a_;
                                    heap[r-1] = sw ? c_ : a_;
                                    heap[r]   = sw ? a_ : c_;
                                }
                                unsigned int h16 = (unsigned int)(heap[16] >> 32);
                                thrF = __uint_as_float((h16 & 0x80000000u) ? (h16 ^ 0x80000000u)
                                                                           : ~h16);
                                float L   = __fmaf_rn(-1e-4f, thrF, thrF) - 1e-6f;
                                float sL  = sqrtf(L);
                                float bb2 = sL - si_r;
                                B2 = (bb2 > 0.0f) ? bb2 * bb2 : -1.0f;
                            }
                        }
                    }
                }
                if ((u & 63) == 63 && __all_sync(0xffffffffu, dead)) break;
            }
        }
        if (__syncthreads_and(dead)) break;
    }

    float sx=0,sy=0,sz=0,sxx=0,syy=0,szz=0,sxy=0,sxz=0,syz=0;
    size_t base = ((size_t)((b << 12) + i)) << 4;
    #pragma unroll
    for (int r = 1; r < 17; r++) {
        int j2 = ~((unsigned int)heap[r]);
        float rx = __fsub_rn(xb[j2],         px);
        float ry = __fsub_rn(xb[NPT  + j2],  py);
        float rz = __fsub_rn(xb[2*NPT + j2], pz);
        d_rel[base + (r - 1)] = make_float4(rx, ry, rz, 0.0f);
        sx += rx; sy += ry; sz += rz;
        sxx = fmaf(rx, rx, sxx); syy = fmaf(ry, ry, syy); szz = fmaf(rz, rz, szz);
        sxy = fmaf(rx, ry, sxy); sxz = fmaf(rx, rz, sxz); syz = fmaf(ry, rz, syz);
    }
    float st[9] = {sx, sy, sz, sxx, syy, szz, sxy, sxz, syz};
    int blk = b * 32 + blockIdx.x;
    for (int s = 0; s < 9; s++) {
        __syncthreads();
        red[tid] = st[s];
        __syncthreads();
        for (int off = 64; off; off >>= 1) {
            if (tid < off) red[tid] += red[tid + off];
            __syncthreads();
        }
        if (tid == 0) d_relstats[blk * 9 + s] = red[0];
    }
}

/* ------------------------- 3. fold block-0 conv+BN+relu ------------------ */
__global__ __launch_bounds__(64) void prep_kernel(const float* __restrict__ w1,
                                                  const float* __restrict__ b1,
                                                  const float* __restrict__ gamma,
                                                  const float* __restrict__ beta) {
    __shared__ double S[9];
    int t = threadIdx.x;
    if (t < 9) {
        double acc = 0.0;
        for (int v = 0; v < 256; v++) acc += (double)d_relstats[v * 9 + t];
        S[t] = acc;
    }
    __syncthreads();
    double inv = 1.0 / (double)NCOL;
    double mx = S[0]*inv, my = S[1]*inv, mz = S[2]*inv;
    double cxx = S[3]*inv - mx*mx, cyy = S[4]*inv - my*my, czz = S[5]*inv - mz*mz;
    double cxy = S[6]*inv - mx*my, cxz = S[7]*inv - mx*mz, cyz = S[8]*inv - my*mz;
    double wx = w1[t*3], wy = w1[t*3+1], wz = w1[t*3+2];
    double var = wx*(wx*cxx + 2.0*(wy*cxy + wz*cxz)) + wy*(wy*cyy + 2.0*wz*cyz) + wz*wz*czz;
    double mu  = wx*mx + wy*my + wz*mz + (double)b1[t];
    float aa = gamma[t] * rsqrtf((float)var + 1e-5f);
    float cc = beta[t] - (float)mu * aa;
    d_w0eff[t] = make_float4(aa*(float)wx, aa*(float)wy, aa*(float)wz, fmaf(aa, b1[t], cc));
}

/* -------- shared device code: build A (h0 split) and B (w2 split) -------- */
__device__ __forceinline__ void build_B(char* smraw, const float* __restrict__ w2, int tid) {
    int n = tid >> 1, k0 = (tid & 1) * 32;
    const float* wrow = w2 + n * 64 + k0;
    #pragma unroll
    for (int k = 0; k < 32; k += 4) {
        float4 v = *(const float4*)(wrow + k);
        uint32_t h0, h1, l0, l1;
        split2(v.x, v.y, h0, l0); split2(v.z, v.w, h1, l1);
        uint32_t off = SWZ((uint32_t)(n * 128 + (k0 + k) * 2));
        *(uint2*)(smraw + SM_BHI + off) = make_uint2(h0, h1);
        *(uint2*)(smraw + SM_BLO + off) = make_uint2(l0, l1);
    }
}
__device__ __forceinline__ void build_A(char* smraw, const float4* w0, int tid, int T) {
    float4 rel = d_rel[(size_t)T * 128 + tid];
    #pragma unroll
    for (int c = 0; c < 64; c += 4) {
        float h[4];
        #pragma unroll
        for (int u = 0; u < 4; u++) {
            float4 w = w0[c + u];
            h[u] = fmaxf(fmaf(w.z, rel.z, fmaf(w.y, rel.y, __fmul_rn(w.x, rel.x))) + w.w, 0.0f);
        }
        uint32_t h0, h1, l0, l1;
        split2(h[0], h[1], h0, l0); split2(h[2], h[3], h1, l1);
        uint32_t off = SWZ((uint32_t)(tid * 128 + c * 2));
        *(uint2*)(smraw + SM_AHI + off) = make_uint2(h0, h1);
        *(uint2*)(smraw + SM_ALO + off) = make_uint2(l0, l1);
    }
}
/* 3-term split MMA over K=64 into acc[2][8][4] */
__device__ __forceinline__ void mma_layer(uint32_t smb, int wid, int lane,
                                          float acc[2][8][4]) {
    uint32_t rowA = wid * 32 + (lane & 15);
    uint32_t kbA  = (lane >> 4) * 8;
    uint32_t nB   = ((lane >> 4) * 8) + (lane & 7);
    uint32_t kbB  = ((lane >> 3) & 1) * 8;
    #pragma unroll
    for (int kt = 0; kt < 4; kt++) {
        uint32_t ah[2][4], al[2][4], bh[4][4], bl[4][4];
        #pragma unroll
        for (int mt = 0; mt < 2; mt++) {
            uint32_t off = SWZ((rowA + mt*16)*128 + (kbA + kt*16)*2);
            ldsm4(smb + SM_AHI + off, ah[mt]);
            ldsm4(smb + SM_ALO + off, al[mt]);
        }
        #pragma unroll
        for (int u = 0; u < 4; u++) {
            uint32_t off = SWZ((nB + u*16)*128 + (kbB + kt*16)*2);
            ldsm4(smb + SM_BHI + off, bh[u]);
            ldsm4(smb + SM_BLO + off, bl[u]);
        }
        #pragma unroll
        for (int mt = 0; mt < 2; mt++)
            #pragma unroll
            for (int j = 0; j < 8; j++) {
                int u = j >> 1, h2 = (j & 1) * 2;
                mma_bf16(acc[mt][j], ah[mt], bh[u][h2], bh[u][h2+1]);
                mma_bf16(acc[mt][j], ah[mt], bl[u][h2], bl[u][h2+1]);
                mma_bf16(acc[mt][j], al[mt], bh[u][h2], bh[u][h2+1]);
            }
    }
}

/* ------------------------- 4. GEMM-1: stats-only, 8 tiles/CTA ------------ */
__global__ __launch_bounds__(128, 2) void gemm1_kernel(const float* __restrict__ w2) {
    extern __shared__ char smraw[];
    uint32_t smb = smem_u32(smraw);
    float4* w0     = (float4*)(smraw + SM_W0);
    float*  wstats = (float*)(smraw + SM_STATS);
    int tid = threadIdx.x, wid = tid >> 5, lane = tid & 31;

    if (tid < 64) w0[tid] = d_w0eff[tid];
    build_B(smraw, w2, tid);

    float s0a[8], s1a[8], q0a[8], q1a[8];
    #pragma unroll
    for (int j = 0; j < 8; j++) { s0a[j] = s1a[j] = q0a[j] = q1a[j] = 0.0f; }

    for (int t = 0; t < TPC; t++) {
        __syncthreads();
        build_A(smraw, w0, tid, blockIdx.x * TPC + t);
        __syncthreads();

        float acc[2][8][4];
        #pragma unroll
        for (int mt = 0; mt < 2; mt++)
            #pragma unroll
            for (int j = 0; j < 8; j++)
                #pragma unroll
                for (int v = 0; v < 4; v++) acc[mt][j][v] = 0.0f;
        mma_layer(smb, wid, lane, acc);

        #pragma unroll
        for (int j = 0; j < 8; j++) {
            s0a[j] += (acc[0][j][0] + acc[0][j][2]) + (acc[1][j][0] + acc[1][j][2]);
            s1a[j] += (acc[0][j][1] + acc[0][j][3]) + (acc[1][j][1] + acc[1][j][3]);
            q0a[j] += fmaf(acc[0][j][0], acc[0][j][0], acc[0][j][2]*acc[0][j][2])
                    + fmaf(acc[1][j][0], acc[1][j][0], acc[1][j][2]*acc[1][j][2]);
            q1a[j] += fmaf(acc[0][j][1], acc[0][j][1], acc[0][j][3]*acc[0][j][3])
                    + fmaf(acc[1][j][1], acc[1][j][1], acc[1][j][3]*acc[1][j][3]);
        }
    }

    int q = lane & 3;
    #pragma unroll
    for (int j = 0; j < 8; j++) {
        float s0 = s0a[j], s1 = s1a[j], q0 = q0a[j], q1 = q1a[j];
        #pragma unroll
        for (int off = 4; off <= 16; off <<= 1) {
            s0 += __shfl_xor_sync(0xffffffffu, s0, off);
            s1 += __shfl_xor_sync(0xffffffffu, s1, off);
            q0 += __shfl_xor_sync(0xffffffffu, q0, off);
            q1 += __shfl_xor_sync(0xffffffffu, q1, off);
        }
        if (lane < 4) {
            int c0 = 8*j + 2*q;
            wstats[wid*128 + c0]          = s0;
            wstats[wid*128 + c0 + 1]      = s1;
            wstats[wid*128 + 64 + c0]     = q0;
            wstats[wid*128 + 64 + c0 + 1] = q1;
        }
    }
    __syncthreads();
    float a = wstats[tid] + wstats[128 + tid] + wstats[256 + tid] + wstats[384 + tid];
    d_z1stats[(size_t)blockIdx.x * 128 + tid] = a;
}

/* ------------------------- 5. fold BN-1 (two-stage reduce) --------------- */
__global__ __launch_bounds__(128) void statsA_kernel() {
    int t = threadIdx.x;
    int base = blockIdx.x * 8;
    double a = 0.0;
    for (int v = 0; v < 8; v++) a += (double)d_z1stats[(size_t)(base + v) * 128 + t];
    d_z1stats2[blockIdx.x * 128 + t] = a;
}

__global__ __launch_bounds__(128) void stats1_kernel(const float* __restrict__ gamma,
                                                     const float* __restrict__ beta) {
    __shared__ double S[128];
    int t = threadIdx.x;
    double acc = 0.0;
    #pragma unroll 8
    for (int c = 0; c < 64; c++) acc += d_z1stats2[c * 128 + t];
    S[t] = acc;
    __syncthreads();
    if (t < 64) {
        double mean = S[t] / (double)NCOL;
        double var  = S[64 + t] / (double)NCOL - mean * mean;
        float aa = gamma[t] * rsqrtf((float)var + 1e-5f);
        float cc = beta[t] - (float)mean * aa;
        d_a1c1[t] = make_float2(aa, cc);
    }
}

/* ------------------------- 6. GEMM-2: 8 tiles/CTA, fused epilogue -------- */
__global__ __launch_bounds__(128, 2) void gemm2_kernel(const float* __restrict__ w2,
                                                       const float* __restrict__ b2,
                                                       float* __restrict__ out) {
    extern __shared__ char smraw[];
    uint32_t smb = smem_u32(smraw);
    float4* w0    = (float4*)(smraw + SM_W0);
    float2* ac    = (float2*)(smraw + SM_AC);
    float*  sbias = (float*)(smraw + SM_BIAS);
    int tid = threadIdx.x, wid = tid >> 5, lane = tid & 31;

    if (tid < 64) { w0[tid] = d_w0eff[tid]; ac[tid] = d_a1c1[tid]; sbias[tid] = b2[tid]; }
    build_B(smraw, w2, tid);

    int q = lane & 3;
    uint32_t nB  = ((lane >> 4) * 8) + (lane & 7);
    uint32_t kbB = ((lane >> 3) & 1) * 8;

    for (int t = 0; t < TPC; t++) {
        int T = blockIdx.x * TPC + t;
        __syncthreads();
        build_A(smraw, w0, tid, T);
        __syncthreads();

        float acc1[2][8][4];
        #pragma unroll
        for (int mt = 0; mt < 2; mt++)
            #pragma unroll
            for (int j = 0; j < 8; j++)
                #pragma unroll
                for (int v = 0; v < 4; v++) acc1[mt][j][v] = 0.0f;
        mma_layer(smb, wid, lane, acc1);

        /* BN-1 affine + relu + bf16-split: D-fragments -> A-fragments */
        uint32_t ahf[2][4][4], alf[2][4][4];
        #pragma unroll
        for (int mt = 0; mt < 2; mt++)
            #pragma unroll
            for (int kt = 0; kt < 4; kt++)
                #pragma unroll
                for (int half = 0; half < 2; half++) {
                    int j = 2*kt + half;
                    float2 c0 = ac[8*j + 2*q], c1 = ac[8*j + 2*q + 1];
                    float v0 = fmaxf(fmaf(c0.x, acc1[mt][j][0], c0.y), 0.0f);
                    float v1 = fmaxf(fmaf(c1.x, acc1[mt][j][1], c1.y), 0.0f);
                    float v2 = fmaxf(fmaf(c0.x, acc1[mt][j][2], c0.y), 0.0f);
                    float v3 = fmaxf(fmaf(c1.x, acc1[mt][j][3], c1.y), 0.0f);
                    split2(v0, v1, ahf[mt][kt][half*2],     alf[mt][kt][half*2]);
                    split2(v2, v3, ahf[mt][kt][half*2 + 1], alf[mt][kt][half*2 + 1]);
                }

        float acc2[2][8][4];
        #pragma unroll
        for (int mt = 0; mt < 2; mt++)
            #pragma unroll
            for (int j = 0; j < 8; j++)
                #pragma unroll
                for (int v = 0; v < 4; v++) acc2[mt][j][v] = 0.0f;
        #pragma unroll
        for (int kt = 0; kt < 4; kt++) {
            uint32_t bh[4][4], bl[4][4];
            #pragma unroll
            for (int u = 0; u < 4; u++) {
                uint32_t off = SWZ((nB + u*16)*128 + (kbB + kt*16)*2);
                ldsm4(smb + SM_BHI + off, bh[u]);
                ldsm4(smb + SM_BLO + off, bl[u]);
            }
            #pragma unroll
            for (int mt = 0; mt < 2; mt++)
                #pragma unroll
                for (int j = 0; j < 8; j++) {
                    int u = j >> 1, h2 = (j & 1) * 2;
                    mma_bf16(acc2[mt][j], ahf[mt][kt], bh[u][h2], bh[u][h2+1]);
                    mma_bf16(acc2[mt][j], ahf[mt][kt], bl[u][h2], bl[u][h2+1]);
                    mma_bf16(acc2[mt][j], alf[mt][kt], bh[u][h2], bh[u][h2+1]);
                }
        }

        /* max over each m16 tile (= one point's 16 neighbors) + bias + store */
        #pragma unroll
        for (int mt = 0; mt < 2; mt++) {
            int g  = T * 8 + wid * 2 + mt;
            int bb = g >> 12, ii = g & 4095;
            #pragma unroll
            for (int j = 0; j < 8; j++) {
                float x = fmaxf(acc2[mt][j][0], acc2[mt][j][2]);
                float y = fmaxf(acc2[mt][j][1], acc2[mt][j][3]);
                #pragma unroll
                for (int off = 4; off <= 16; off <<= 1) {
                    x = fmaxf(x, __shfl_xor_sync(0xffffffffu, x, off));
                    y = fmaxf(y, __shfl_xor_sync(0xffffffffu, y, off));
                }
                if (lane < 4) {
                    int c0 = 8*j + 2*lane;
                    out[((size_t)(bb * CH + c0)     << 12) + ii] = x + sbias[c0];
                    out[((size_t)(bb * CH + c0 + 1) << 12) + ii] = y + sbias[c0 + 1];
                }
            }
        }
    }
}

/* ------------------------- launch ---------------------------------------- */
extern "C" void kernel_launch(void* const* d_in, const int* in_sizes, int n_in,
                              void* d_out, int out_size) {
    const float* xyz   = (const float*)d_in[0];
    const float* w1    = (const float*)d_in[1];
    const float* b1    = (const float*)d_in[2];
    const float* w2    = (const float*)d_in[3];
    const float* b2    = (const float*)d_in[4];
    const float* gamma = (const float*)d_in[5];
    const float* beta  = (const float*)d_in[6];
    float* out = (float*)d_out;

    cudaFuncSetAttribute(gemm1_kernel, cudaFuncAttributeMaxDynamicSharedMemorySize, SMEM_G);
    cudaFuncSetAttribute(gemm2_kernel, cudaFuncAttributeMaxDynamicSharedMemorySize, SMEM_G);

    sort_kernel<<<BATCH, 1024>>>(xyz);
    knn_kernel<<<dim3(32, BATCH), 128>>>(xyz);
    prep_kernel<<<1, 64>>>(w1, b1, gamma, beta);
    gemm1_kernel<<<NGRID, 128, SMEM_G>>>(w2);
    statsA_kernel<<<64, 128>>>();
    stats1_kernel<<<1, 128>>>(gamma, beta);
    gemm2_kernel<<<NGRID, 128, SMEM_G>>>(w2, b2, out);
}